// round 5
// baseline (speedup 1.0000x reference)
#include <cuda_runtime.h>
#include <cuda_bf16.h>

// Cost volume: out[n,c,d,h,w] = left[n,c,h,w] * right[n,c,h,w-d]  (0 if w<d)
// N=2 C=32 H=136 W=240 D=48, fp32.
//
// R4 steady state: 6.75 TB/s pure write stream (84% of HBM spec); L1% is the
// store-wavefront floor. R5: amortize per-CTA staging/sync/epilogue — 2 rows
// per CTA, 512 threads, grid halved to 4352. Inner scheme unchanged:
// d = 4q+s -> 2 aligned LDS.128 serve 4 disparities; STG.128 streaming (__stcs).

#define NW   240
#define NH   136
#define NC   32
#define NN   2
#define ND   48
#define W4   60              // float4 columns per row
#define PADF 64              // zero floats in front of P
#define ROWSZ (PADF + NW)    // 304
#define THREADS 512

__global__ __launch_bounds__(THREADS, 4)
void cost_volume_kernel(const float* __restrict__ left,
                        const float* __restrict__ right,
                        float* __restrict__ out) {
    // Two padded right rows: buf[r][i] = P_r[i - PADF]
    __shared__ __align__(16) float buf[2][ROWSZ];

    const int pair = blockIdx.x;         // handles rows 2*pair, 2*pair+1
    const int row0 = pair * 2;           // NH even => both rows share nc
    const int tid  = threadIdx.x;
    const int lane = tid & 31;
    const int wid  = tid >> 5;           // 0..15

    // Cooperative staging of both padded rows (coalesced, conflict-free).
    const float* rbase = right + (size_t)row0 * NW;
    for (int i = tid; i < 2 * ROWSZ; i += THREADS) {
        const int r  = i / ROWSZ;
        const int j  = i - r * ROWSZ;
        buf[r][j] = (j < PADF) ? 0.0f : rbase[(size_t)r * NW + j - PADF];
    }
    __syncthreads();

    // Warp mapping: rowsel = wid&1, half = (wid>>1)&1, stripe = wid>>2 (0..3)
    const int rowsel = wid & 1;
    const int half   = (wid >> 1) & 1;
    const int stripe = wid >> 2;

    const int c = lane + (half << 5);    // float4 column 0..63
    if (c >= W4) return;                 // no collectives below

    const int row = row0 + rowsel;
    const int h   = row % NH;
    const int nc  = row / NH;

    const float4 l4 = reinterpret_cast<const float4*>(left + (size_t)row * NW)[c];

    float* obase = out + ((size_t)nc * ND * NH + h) * NW + 4 * c;
    const float* P = buf[rowsel] + PADF; // P[x], x down to -64 valid

    #pragma unroll
    for (int g = 0; g < 3; g++) {
        const int q = 3 * stripe + g;    // d-group: d = 4q+s, s = 0..3
        const float4 Y = *reinterpret_cast<const float4*>(P + 4 * (c - q));
        const float4 X = *reinterpret_cast<const float4*>(P + 4 * (c - q - 1));
        const float yv[4] = {Y.x, Y.y, Y.z, Y.w};
        const float xv[4] = {X.x, X.y, X.z, X.w};

        #pragma unroll
        for (int s = 0; s < 4; s++) {
            const int d = 4 * q + s;
            float4 v;
            // out[4c+i] uses P[4c+i-d] = (i>=s) ? Y[i-s] : X[i+4-s]  (static)
            v.x = l4.x * ((0 >= s) ? yv[0] : xv[4 - s]);
            v.y = l4.y * ((1 >= s) ? yv[(1 - s) & 3] : xv[(5 - s) & 3]);
            v.z = l4.z * ((2 >= s) ? yv[(2 - s) & 3] : xv[(6 - s) & 3]);
            v.w = l4.w * ((3 >= s) ? yv[(3 - s) & 3] : xv[(7 - s) & 3]);
            __stcs(reinterpret_cast<float4*>(obase + (size_t)d * (NH * NW)), v);
        }
    }
}

extern "C" void kernel_launch(void* const* d_in, const int* in_sizes, int n_in,
                              void* d_out, int out_size) {
    const float* left  = (const float*)d_in[0];
    const float* right = (const float*)d_in[1];
    float* out = (float*)d_out;

    const int grid = (NN * NC * NH) / 2; // 4352 CTAs, two rows each
    cost_volume_kernel<<<grid, THREADS>>>(left, right, out);
}